// round 5
// baseline (speedup 1.0000x reference)
#include <cuda_runtime.h>
#include <cuda_bf16.h>
#include <math.h>
#include <cstdint>

#define BATCH 32
#define CCH   3
#define HH    224
#define NTOK  196
#define PD    768
#define DIM   512
#define NCLS  1000
#define NP    224
#define NPS   (NP*NP)
#define KP    256
#define SLK_M (64*NP)
#define SLK_QV (64*DIM)
#define ITERS 50
#define LNEPS 1e-5f

typedef unsigned long long u64;
typedef unsigned int u32;

// ---------------- scratch ----------------
__device__ float g_x[BATCH*NTOK*PD];
__device__ float g_Q[BATCH*NP*DIM + SLK_QV];
__device__ float g_V[BATCH*NP*DIM + SLK_QV];
__device__ float g_A[BATCH*NPS + SLK_M];
__device__ float g_Minv[BATCH*NPS + SLK_M];
__device__ float g_P[BATCH*NPS + SLK_M];
__device__ float g_Z[BATCH*NPS + SLK_M];
__device__ __align__(16) __nv_bfloat16 g_MH[BATCH*NP*KP];
__device__ __align__(16) __nv_bfloat16 g_ML[BATCH*NP*KP];
__device__ float g_pooled[BATCH*DIM];

// ---------------- helpers ----------------
__device__ __forceinline__ u32 smem_u32(const void* p) {
    u32 a; asm("{ .reg .u64 t; cvta.to.shared.u64 t, %1; cvt.u32.u64 %0, t; }" : "=r"(a) : "l"(p));
    return a;
}
__device__ __forceinline__ void cp16(u32 dst, const void* src) {
    asm volatile("cp.async.ca.shared.global [%0], [%1], 16;" :: "r"(dst), "l"(src));
}

__device__ __forceinline__ void block_reduce2(float& s, float& s2) {
    __shared__ float sh[2][32];
    int tid = threadIdx.x;
#pragma unroll
    for (int o = 16; o; o >>= 1) {
        s  += __shfl_xor_sync(0xffffffffu, s, o);
        s2 += __shfl_xor_sync(0xffffffffu, s2, o);
    }
    __syncthreads();
    if ((tid & 31) == 0) { sh[0][tid >> 5] = s; sh[1][tid >> 5] = s2; }
    __syncthreads();
    int nw = blockDim.x >> 5;
    float a = 0.f, b = 0.f;
    for (int i = 0; i < nw; i++) { a += sh[0][i]; b += sh[1][i]; }
    s = a; s2 = b;
}

// ---------------- patchify + LN(768) + pos ----------------
__global__ void k_patch_ln(const float* __restrict__ img,
                           const float* __restrict__ lg,
                           const float* __restrict__ lb,
                           const float* __restrict__ pos) {
    int blk = blockIdx.x;
    int b = blk / NTOK, n = blk % NTOK;
    int hh = n / 14, ww = n % 14;
    int tid = threadIdx.x;
    float v[3];
    float s = 0.f, s2 = 0.f;
#pragma unroll
    for (int t = 0; t < 3; t++) {
        int d = tid + t * 256;
        int c = d >> 8, r = d & 255, ph = r >> 4, pw = r & 15;
        float x = img[((b * CCH + c) * HH + hh * 16 + ph) * HH + ww * 16 + pw];
        v[t] = x; s += x; s2 += x * x;
    }
    block_reduce2(s, s2);
    float mu = s * (1.f / 768.f);
    float var = s2 * (1.f / 768.f) - mu * mu;
    float rs = rsqrtf(var + LNEPS);
#pragma unroll
    for (int t = 0; t < 3; t++) {
        int d = tid + t * 256;
        g_x[(b * NTOK + n) * PD + d] = (v[t] - mu) * rs * lg[d] + lb[d] + pos[n * PD + d];
    }
}

// ---------------- projection GEMM ----------------
__global__ void k_proj(const float* __restrict__ X, const float* __restrict__ W,
                       const float* __restrict__ bias, float* __restrict__ out) {
    __shared__ float As[16][68], Bs[16][68];
    int m0 = blockIdx.x * 64, n0 = blockIdx.y * 64;
    int tid = threadIdx.x;
    int tx = tid & 15, ty = tid >> 4;
    int arow = tid >> 2, acg = (tid & 3) * 4;
    int brow = tid >> 4, bcol = (tid & 15) * 4;
    float acc[4][4] = {};
    for (int k0 = 0; k0 < PD; k0 += 16) {
        float4 a = *(const float4*)&X[(m0 + arow) * PD + k0 + acg];
        As[acg + 0][arow] = a.x; As[acg + 1][arow] = a.y;
        As[acg + 2][arow] = a.z; As[acg + 3][arow] = a.w;
        *(float4*)&Bs[brow][bcol] = *(const float4*)&W[(k0 + brow) * DIM + n0 + bcol];
        __syncthreads();
#pragma unroll
        for (int kk = 0; kk < 16; kk++) {
            float4 a4 = *(float4*)&As[kk][ty * 4];
            float4 b4 = *(float4*)&Bs[kk][tx * 4];
            acc[0][0] += a4.x * b4.x; acc[0][1] += a4.x * b4.y; acc[0][2] += a4.x * b4.z; acc[0][3] += a4.x * b4.w;
            acc[1][0] += a4.y * b4.x; acc[1][1] += a4.y * b4.y; acc[1][2] += a4.y * b4.z; acc[1][3] += a4.y * b4.w;
            acc[2][0] += a4.z * b4.x; acc[2][1] += a4.z * b4.y; acc[2][2] += a4.z * b4.z; acc[2][3] += a4.z * b4.w;
            acc[3][0] += a4.w * b4.x; acc[3][1] += a4.w * b4.y; acc[3][2] += a4.w * b4.z; acc[3][3] += a4.w * b4.w;
        }
        __syncthreads();
    }
#pragma unroll
    for (int i = 0; i < 4; i++) {
        int gm = m0 + ty * 4 + i;
        int b = gm / NTOK, nn = gm % NTOK;
#pragma unroll
        for (int j = 0; j < 4; j++) {
            int gc = n0 + tx * 4 + j;
            out[(b * NP + nn) * DIM + gc] = acc[i][j] + bias[gc];
        }
    }
}

// ---------------- LN over 512 ----------------
__global__ void k_ln512(float* __restrict__ buf, const float* __restrict__ lg,
                        const float* __restrict__ lb, float scale) {
    int blk = blockIdx.x;
    int b = blk / NTOK, n = blk % NTOK;
    float* row = buf + (b * NP + n) * DIM;
    int tid = threadIdx.x;
    float4 v = ((float4*)row)[tid];
    float s = v.x + v.y + v.z + v.w;
    float s2 = v.x * v.x + v.y * v.y + v.z * v.z + v.w * v.w;
    block_reduce2(s, s2);
    float mu = s * (1.f / 512.f);
    float rs = rsqrtf(s2 * (1.f / 512.f) - mu * mu + LNEPS);
    float4 g4 = ((const float4*)lg)[tid], b4 = ((const float4*)lb)[tid];
    v.x = ((v.x - mu) * rs * g4.x + b4.x) * scale;
    v.y = ((v.y - mu) * rs * g4.y + b4.y) * scale;
    v.z = ((v.z - mu) * rs * g4.z + b4.z) * scale;
    v.w = ((v.w - mu) * rs * g4.w + b4.w) * scale;
    ((float4*)row)[tid] = v;
}

// ---------------- Gram GEMMs ----------------
__global__ void k_gram(const float* __restrict__ Abase, const float* __restrict__ Bbase,
                       float* __restrict__ out, int mode) {
    int b = blockIdx.z;
    const float* Ab = Abase + b * NP * DIM;
    const float* Bb = Bbase + b * NP * DIM;
    __shared__ float As[16][68], Bs[16][68];
    int m0 = blockIdx.x * 64, n0 = blockIdx.y * 64;
    int tid = threadIdx.x;
    int tx = tid & 15, ty = tid >> 4;
    int arow = tid >> 2, acg = (tid & 3) * 4;
    float acc[4][4] = {};
    for (int k0 = 0; k0 < DIM; k0 += 16) {
        float4 a = *(const float4*)&Ab[(m0 + arow) * DIM + k0 + acg];
        As[acg + 0][arow] = a.x; As[acg + 1][arow] = a.y;
        As[acg + 2][arow] = a.z; As[acg + 3][arow] = a.w;
        float4 bb = *(const float4*)&Bb[(n0 + arow) * DIM + k0 + acg];
        Bs[acg + 0][arow] = bb.x; Bs[acg + 1][arow] = bb.y;
        Bs[acg + 2][arow] = bb.z; Bs[acg + 3][arow] = bb.w;
        __syncthreads();
#pragma unroll
        for (int kk = 0; kk < 16; kk++) {
            float4 a4 = *(float4*)&As[kk][ty * 4];
            float4 b4 = *(float4*)&Bs[kk][tx * 4];
            acc[0][0] += a4.x * b4.x; acc[0][1] += a4.x * b4.y; acc[0][2] += a4.x * b4.z; acc[0][3] += a4.x * b4.w;
            acc[1][0] += a4.y * b4.x; acc[1][1] += a4.y * b4.y; acc[1][2] += a4.y * b4.z; acc[1][3] += a4.y * b4.w;
            acc[2][0] += a4.z * b4.x; acc[2][1] += a4.z * b4.y; acc[2][2] += a4.z * b4.z; acc[2][3] += a4.z * b4.w;
            acc[3][0] += a4.w * b4.x; acc[3][1] += a4.w * b4.y; acc[3][2] += a4.w * b4.z; acc[3][3] += a4.w * b4.w;
        }
        __syncthreads();
    }
#pragma unroll
    for (int i = 0; i < 4; i++) {
        int gm = m0 + ty * 4 + i;
        if (gm >= NP) continue;
#pragma unroll
        for (int j = 0; j < 4; j++) {
            int gn = n0 + tx * 4 + j;
            if (gn >= NP) continue;
            float val;
            if (mode == 0) {
                val = 2.f * acc[i][j] + ((gm == gn) ? 1.f : 0.f);
            } else {
                val = (gm < NTOK && gn < NTOK) ? (-2.f * acc[i][j] + (1.f / 196.f)) : 0.f;
            }
            out[b * NPS + gm * NP + gn] = val;
        }
    }
}

// ---------------- Gauss-Jordan inverse ----------------
extern __shared__ float sA[];
__global__ void k_inv(const float* __restrict__ Ain, float* __restrict__ Mout) {
    int b = blockIdx.x;
    int tid = threadIdx.x;
    const float* A = Ain + b * NPS;
    float* Mi = Mout + b * NPS;
    for (int i = tid; i < 196 * 196; i += 512) {
        int r = i / 196, c = i % 196;
        sA[r * 197 + c] = A[r * NP + c];
    }
    __shared__ float s_pivinv;
    int wid = tid >> 5, lane = tid & 31;
    for (int k = 0; k < 196; k++) {
        __syncthreads();
        if (tid == 0) s_pivinv = 1.0f / sA[k * 197 + k];
        __syncthreads();
        float pv = s_pivinv;
        if (tid < 196)
            sA[k * 197 + tid] = ((tid == k) ? 1.0f : sA[k * 197 + tid]) * pv;
        __syncthreads();
        float rk[7];
#pragma unroll
        for (int t = 0; t < 7; t++) {
            int j = lane + 32 * t;
            rk[t] = (j < 196) ? sA[k * 197 + j] : 0.f;
        }
        for (int i = wid; i < 196; i += 16) {
            if (i == k) continue;
            float f = sA[i * 197 + k];
#pragma unroll
            for (int t = 0; t < 7; t++) {
                int j = lane + 32 * t;
                if (j < 196) {
                    float val = ((j == k) ? 0.f : sA[i * 197 + j]) - f * rk[t];
                    sA[i * 197 + j] = val;
                }
            }
        }
    }
    __syncthreads();
    for (int i = tid; i < NPS; i += 512) {
        int r = i / NP, c = i % NP;
        Mi[i] = (r < 196 && c < 196) ? sA[r * 197 + c] : 0.f;
    }
}

// ---------------- split Minv -> bf16 hi/lo, padded [B][224][256] ----------------
__global__ void k_minv_split(const float* __restrict__ Minv) {
    int idx = blockIdx.x * 256 + threadIdx.x;
    if (idx >= BATCH * NP * KP) return;
    int k = idx & (KP - 1);
    int r = (idx >> 8) % NP;
    int b = idx / (NP * KP);
    float v = (k < NP) ? Minv[b * NPS + r * NP + k] : 0.f;
    __nv_bfloat16 h = __float2bfloat16(v);
    g_MH[idx] = h;
    g_ML[idx] = __float2bfloat16(v - __bfloat162float(h));
}

// =====================================================================
// FUSED persistent ADMM: all 50 iterations in one kernel.
// Grid (7 row-groups, 32 batches), 256 threads (8 warps: 2m x 4n).
// CTA owns rows [rg*32, rg*32+32) of batch b. z,u live in registers,
// mapped exactly to mma accumulator positions. Per iteration only Minv
// hi/lo streams from L2 (cp.async double-buffered 16-wide k-chunks).
// =====================================================================
#define ASTR 232      // sA bf16 stride
#define BSTR 24       // sB bf16 stride (16 data + 8 pad)
#define PSTR 228      // sP float stride
// bf16-unit offsets: sAh 0 (7424), sAl 7424, sB 14848 (4 x 5376: buf*10752 + hilo*5376)
// sP (float) at bf16 offset 36352 (byte 72704), 32*228*4 = 29184 B
#define FUSED_SMEM (72704 + 29184)

__device__ __forceinline__ void mma16816(float* d, const u32* a, const u32* b) {
    asm volatile("mma.sync.aligned.m16n8k16.row.col.f32.bf16.bf16.f32 "
        "{%0,%1,%2,%3}, {%4,%5,%6,%7}, {%8,%9}, {%0,%1,%2,%3};"
        : "+f"(d[0]), "+f"(d[1]), "+f"(d[2]), "+f"(d[3])
        : "r"(a[0]), "r"(a[1]), "r"(a[2]), "r"(a[3]), "r"(b[0]), "r"(b[1]));
}

__global__ __launch_bounds__(256, 2) void k_admm_fused(
    const float* __restrict__ Pg,
    const __nv_bfloat16* __restrict__ MH, const __nv_bfloat16* __restrict__ ML,
    float* __restrict__ Zout)
{
    extern __shared__ __nv_bfloat16 sm[];
    __nv_bfloat16* sAh = sm;
    __nv_bfloat16* sAl = sm + 7424;
    float* sP = (float*)(sm + 36352);
    u32 smb = smem_u32(sm);

    int tid = threadIdx.x;
    int lane = tid & 31, wid = tid >> 5;
    int wm = wid & 1, wn = wid >> 1;
    int grp = lane >> 2, qid = lane & 3;
    int rg = blockIdx.x, b = blockIdx.y;

    // P -> smem (rows rg*32..+32, all 224 cols; contiguous in global)
    const float* Pbase = Pg + (size_t)b * NPS + rg * 32 * NP;
    for (int i = tid; i < 32 * 224; i += 256) {
        int r = i / 224, c = i - r * 224;
        sP[r * PSTR + c] = Pbase[i];
    }

    const __nv_bfloat16* MHb = MH + (size_t)b * NP * KP;
    const __nv_bfloat16* MLb = ML + (size_t)b * NP * KP;

    const int arow = wm * 16 + grp;           // base row (0..31), +8 for rr=1
    const int cbase = wn * 56 + qid * 2;      // base col, +nt*8

    float z[28], u[28];
#pragma unroll
    for (int i = 0; i < 28; i++) { z[i] = 0.f; u[i] = 0.f; }

    __syncthreads();   // sP ready

    for (int iter = 0; iter < ITERS; iter++) {
        // ---- build A = (z - u - p) split to bf16 hi/lo, at my acc positions ----
#pragma unroll
        for (int nt = 0; nt < 7; nt++) {
            int cb = cbase + nt * 8;
#pragma unroll
            for (int rr = 0; rr < 2; rr++) {
                int i0 = nt * 4 + rr * 2;
                int r = arow + rr * 8;
                float p0 = sP[r * PSTR + cb];
                float p1 = sP[r * PSTR + cb + 1];
                float r0 = z[i0] - u[i0] - p0;
                float r1 = z[i0 + 1] - u[i0 + 1] - p1;
                __nv_bfloat162 h2 = __floats2bfloat162_rn(r0, r1);
                float l0 = r0 - __bfloat162float(h2.x);
                float l1 = r1 - __bfloat162float(h2.y);
                __nv_bfloat162 l2 = __floats2bfloat162_rn(l0, l1);
                *(u32*)&sAh[r * ASTR + cb] = *(u32*)&h2;
                *(u32*)&sAl[r * ASTR + cb] = *(u32*)&l2;
            }
        }
        // prefetch B chunk 0 into buf 0
        {
            if (tid < 224) {
                const __nv_bfloat16* sh = MHb + tid * KP;
                const __nv_bfloat16* sl = MLb + tid * KP;
                u32 dh = smb + (14848 + tid * BSTR) * 2;
                cp16(dh, sh); cp16(dh + 16, sh + 8);
                u32 dl = dh + 5376 * 2;
                cp16(dl, sl); cp16(dl + 16, sl + 8);
            }
            asm volatile("cp.async.commit_group;" ::: "memory");
        }
        __syncthreads();   // A visible to all warps

        float acc[7][4];
#pragma unroll
        for (int nt = 0; nt < 7; nt++)
#pragma unroll
            for (int j = 0; j < 4; j++) acc[nt][j] = 0.f;

        for (int kc = 0; kc < 14; kc++) {
            asm volatile("cp.async.wait_group 0;" ::: "memory");
            __syncthreads();   // chunk kc visible; all warps done with mma(kc-1)
            if (kc < 13) {
                if (tid < 224) {
                    const __nv_bfloat16* sh = MHb + tid * KP + (kc + 1) * 16;
                    const __nv_bfloat16* sl = MLb + tid * KP + (kc + 1) * 16;
                    u32 dh = smb + (14848 + ((kc + 1) & 1) * 10752 + tid * BSTR) * 2;
                    cp16(dh, sh); cp16(dh + 16, sh + 8);
                    u32 dl = dh + 5376 * 2;
                    cp16(dl, sl); cp16(dl + 16, sl + 8);
                }
                asm volatile("cp.async.commit_group;" ::: "memory");
            }
            const __nv_bfloat16* bhp = sm + 14848 + (kc & 1) * 10752;
            const __nv_bfloat16* blp = bhp + 5376;
            int ab = arow * ASTR + kc * 16 + qid * 2;
            u32 ah[4], al[4];
            ah[0] = *(const u32*)&sAh[ab];
            ah[1] = *(const u32*)&sAh[ab + 8 * ASTR];
            ah[2] = *(const u32*)&sAh[ab + 8];
            ah[3] = *(const u32*)&sAh[ab + 8 * ASTR + 8];
            al[0] = *(const u32*)&sAl[ab];
            al[1] = *(const u32*)&sAl[ab + 8 * ASTR];
            al[2] = *(const u32*)&sAl[ab + 8];
            al[3] = *(const u32*)&sAl[ab + 8 * ASTR + 8];
#pragma unroll
            for (int nt = 0; nt < 7; nt++) {
                int bb = (wn * 56 + nt * 8 + grp) * BSTR + qid * 2;
                u32 bh[2], bl[2];
                bh[0] = *(const u32*)&bhp[bb];
                bh[1] = *(const u32*)&bhp[bb + 8];
                bl[0] = *(const u32*)&blp[bb];
                bl[1] = *(const u32*)&blp[bb + 8];
                mma16816(acc[nt], ah, bh);
                mma16816(acc[nt], al, bh);
                mma16816(acc[nt], ah, bl);
            }
        }
        __syncthreads();   // all mma done before next iter overwrites sA/sB

        // ---- z/u update (pure registers) ----
#pragma unroll
        for (int nt = 0; nt < 7; nt++)
#pragma unroll
            for (int j = 0; j < 4; j++) {
                int i = nt * 4 + j;
                float x = acc[nt][j];
                float zn = fminf(fmaxf(x + u[i], 0.f), 1.f);
                u[i] = u[i] + x - zn;
                z[i] = zn;
            }
    }

    // ---- write final Z ----
    float* Zo = Zout + (size_t)b * NPS + rg * 32 * NP;
#pragma unroll
    for (int nt = 0; nt < 7; nt++) {
        int cb = cbase + nt * 8;
#pragma unroll
        for (int rr = 0; rr < 2; rr++) {
            int i0 = nt * 4 + rr * 2;
            *(float2*)&Zo[(arow + rr * 8) * NP + cb] = make_float2(z[i0], z[i0 + 1]);
        }
    }
}

// ---------------- pooled ----------------
__global__ void k_pool(const float* __restrict__ Zfin) {
    int b = blockIdx.x;
    int tid = threadIdx.x;
    __shared__ float sS[196], sW[196];
    const float* Zb = Zfin + b * NPS;
    if (tid < 196) {
        float s = 0.f;
        const float* row = Zb + tid * NP;
        for (int m = 0; m < 196; m++) s += fabsf(row[m]);
        sS[tid] = s + 1e-10f;
    }
    __syncthreads();
    if (tid < 196) {
        float w = 0.f;
        for (int n = 0; n < 196; n++) w += Zb[n * NP + tid] / sS[n];
        sW[tid] = w * (1.f / 196.f);
    }
    __syncthreads();
    const float* Vb = g_V + b * NP * DIM;
    for (int d = tid; d < DIM; d += 256) {
        float acc = 0.f;
        for (int m = 0; m < 196; m++) acc += sW[m] * Vb[m * DIM + d];
        g_pooled[b * DIM + d] = acc;
    }
}

// ---------------- head ----------------
__global__ void k_head(const float* __restrict__ lg, const float* __restrict__ lb,
                       const float* __restrict__ W, const float* __restrict__ bias,
                       float* __restrict__ out) {
    int b = blockIdx.x;
    int tid = threadIdx.x;
    __shared__ float sx[DIM];
    float s = 0.f, s2 = 0.f;
    for (int d = tid; d < DIM; d += 256) {
        float v = g_pooled[b * DIM + d];
        sx[d] = v; s += v; s2 += v * v;
    }
    block_reduce2(s, s2);
    float mu = s * (1.f / 512.f);
    float rs = rsqrtf(s2 * (1.f / 512.f) - mu * mu + LNEPS);
    __syncthreads();
    for (int d = tid; d < DIM; d += 256) sx[d] = (sx[d] - mu) * rs * lg[d] + lb[d];
    __syncthreads();
    float lgts[4];
    float mx = -1e30f;
#pragma unroll
    for (int t = 0; t < 4; t++) {
        int c = tid + t * 256;
        if (c < NCLS) {
            float acc = bias[c];
            for (int d = 0; d < DIM; d++) acc += sx[d] * W[d * NCLS + c];
            lgts[t] = acc;
            mx = fmaxf(mx, acc);
        } else lgts[t] = -1e30f;
    }
    __shared__ float red[32];
    for (int o = 16; o; o >>= 1) mx = fmaxf(mx, __shfl_xor_sync(0xffffffffu, mx, o));
    if ((tid & 31) == 0) red[tid >> 5] = mx;
    __syncthreads();
    float bm = red[0];
    for (int i = 1; i < 8; i++) bm = fmaxf(bm, red[i]);
    float es = 0.f;
#pragma unroll
    for (int t = 0; t < 4; t++) {
        int c = tid + t * 256;
        if (c < NCLS) { lgts[t] = expf(lgts[t] - bm); es += lgts[t]; }
    }
    float dummy = 0.f;
    block_reduce2(es, dummy);
#pragma unroll
    for (int t = 0; t < 4; t++) {
        int c = tid + t * 256;
        if (c < NCLS) out[b * NCLS + c] = lgts[t] / es;
    }
}

// ---------------- host ----------------
extern "C" void kernel_launch(void* const* d_in, const int* in_sizes, int n_in,
                              void* d_out, int out_size) {
    const float* img    = (const float*)d_in[0];
    const float* ln_pg  = (const float*)d_in[1];
    const float* ln_pb  = (const float*)d_in[2];
    const float* wq_w   = (const float*)d_in[3];
    const float* wq_b   = (const float*)d_in[4];
    const float* lnq_g  = (const float*)d_in[5];
    const float* lnq_b  = (const float*)d_in[6];
    const float* wv_w   = (const float*)d_in[7];
    const float* wv_b   = (const float*)d_in[8];
    const float* lnv_g  = (const float*)d_in[9];
    const float* lnv_b  = (const float*)d_in[10];
    const float* pos    = (const float*)d_in[11];
    const float* mlp_g  = (const float*)d_in[12];
    const float* mlp_b  = (const float*)d_in[13];
    const float* mlp_w  = (const float*)d_in[14];
    const float* mlp_bs = (const float*)d_in[15];
    float* out = (float*)d_out;

    float *px, *pq, *pv, *pa, *pm, *pp, *pz;
    __nv_bfloat16 *pmh, *pml;
    cudaGetSymbolAddress((void**)&px, g_x);
    cudaGetSymbolAddress((void**)&pq, g_Q);
    cudaGetSymbolAddress((void**)&pv, g_V);
    cudaGetSymbolAddress((void**)&pa, g_A);
    cudaGetSymbolAddress((void**)&pm, g_Minv);
    cudaGetSymbolAddress((void**)&pp, g_P);
    cudaGetSymbolAddress((void**)&pz, g_Z);
    cudaGetSymbolAddress((void**)&pmh, g_MH);
    cudaGetSymbolAddress((void**)&pml, g_ML);

    cudaFuncSetAttribute(k_inv, cudaFuncAttributeMaxDynamicSharedMemorySize, 196 * 197 * 4);
    cudaFuncSetAttribute(k_admm_fused, cudaFuncAttributeMaxDynamicSharedMemorySize, FUSED_SMEM);

    k_patch_ln<<<BATCH * NTOK, 256>>>(img, ln_pg, ln_pb, pos);
    dim3 gp(98, 8);
    k_proj<<<gp, 256>>>(px, wq_w, wq_b, pq);
    k_proj<<<gp, 256>>>(px, wv_w, wv_b, pv);
    k_ln512<<<BATCH * NTOK, 128>>>(pq, lnq_g, lnq_b, 1.0f);
    k_ln512<<<BATCH * NTOK, 128>>>(pv, lnv_g, lnv_b, 1.0f / 196.0f);
    dim3 gg(4, 4, BATCH);
    k_gram<<<gg, 256>>>(pv, pv, pa, 0);
    k_gram<<<gg, 256>>>(pq, pv, pp, 1);
    k_inv<<<BATCH, 512, 196 * 197 * 4>>>(pa, pm);
    k_minv_split<<<(BATCH * NP * KP + 255) / 256, 256>>>(pm);
    // fused ADMM: one launch, 50 iterations inside
    k_admm_fused<<<dim3(7, BATCH), 256, FUSED_SMEM>>>(pp, pmh, pml, pz);
    k_pool<<<BATCH, 256>>>(pz);
    k_head<<<BATCH, 256>>>(mlp_g, mlp_b, mlp_w, mlp_bs, out);
}